// round 5
// baseline (speedup 1.0000x reference)
#include <cuda_runtime.h>
#include <cuda_bf16.h>
#include <cstdint>

#define BB 256
#define NN 256
#define MM 256
#define DD 1024
#define RBAND 128
#define BIGF 1e30f

// dist in DIAGONAL layout: [b][k=i+j][j], 512*256 floats per batch
__device__ float g_distD[(size_t)BB * 512 * 256];

static __device__ __forceinline__ uint32_t smem_u32(const void* p) {
    uint32_t a;
    asm("{ .reg .u64 t; cvta.to.shared.u64 t, %1; cvt.u32.u64 %0, t; }" : "=r"(a) : "l"(p));
    return a;
}
static __device__ __forceinline__ void cp16(uint32_t dst, const void* src) {
    asm volatile("cp.async.cg.shared.global [%0], [%1], 16;\n" ::"r"(dst), "l"(src) : "memory");
}
static __device__ __forceinline__ void ldsm_x4(uint32_t& r0, uint32_t& r1, uint32_t& r2,
                                               uint32_t& r3, uint32_t addr) {
    asm volatile("ldmatrix.sync.aligned.m8n8.x4.shared.b16 {%0,%1,%2,%3}, [%4];"
                 : "=r"(r0), "=r"(r1), "=r"(r2), "=r"(r3) : "r"(addr));
}
static __device__ __forceinline__ uint2 cvt_f4_bf16(float4 a) {
    __nv_bfloat162 p0 = __floats2bfloat162_rn(a.x, a.y);
    __nv_bfloat162 p1 = __floats2bfloat162_rn(a.z, a.w);
    uint2 w;
    w.x = *reinterpret_cast<unsigned int*>(&p0);
    w.y = *reinterpret_cast<unsigned int*>(&p1);
    return w;
}

// ---------------------------------------------------------------------------
// Fused kernel: normalization + batched GEMM sim = A @ B^T.
// Raw fp32 reads, bf16 conversion while staging to smem, per-row sum-of-squares
// accumulated during loads. Epilogue: dist = 1-clamp(sim*invA*invB) written in
// DIAGONAL layout via smem staging (two 64-row halves, warp-per-diagonal
// copy-out -> coalesced global stores, conflict-free smem).
// ---------------------------------------------------------------------------
#define KT 32
#define LDP 40
#define STG_LD 132   // stage row stride in floats (131%32=3 -> diag reads conflict-free)

union SmemU {
    struct {
        __nv_bfloat16 As[2][128 * LDP];
        __nv_bfloat16 Bs[2][128 * LDP];
    } m;
    float stage[64 * STG_LD];
};

__global__ __launch_bounds__(256, 2) void gemm_kernel(const float* __restrict__ s1,
                                                      const float* __restrict__ s2) {
    __shared__ SmemU su;
    __shared__ float invA_s[128];
    __shared__ float invB_s[128];

    int b  = blockIdx.z;
    int i0 = blockIdx.x * 128;
    int j0 = blockIdx.y * 128;
    int t    = threadIdx.x;
    int lane = t & 31;
    int w    = t >> 5;
    int wm = w & 1;
    int wn = w >> 1;
    int gid = lane >> 2;
    int tig = lane & 3;

    const float* Ag = s1 + (size_t)b * NN * DD + (size_t)i0 * DD;
    const float* Bg = s2 + (size_t)b * MM * DD + (size_t)j0 * DD;

    int lr = t >> 3;
    int lc = (t & 7) * 4;

    float acc[4][4][4];
#pragma unroll
    for (int mt = 0; mt < 4; mt++)
#pragma unroll
        for (int nt = 0; nt < 4; nt++)
#pragma unroll
            for (int c = 0; c < 4; c++) acc[mt][nt][c] = 0.f;

    float ssA[4] = {0.f, 0.f, 0.f, 0.f};
    float ssB[4] = {0.f, 0.f, 0.f, 0.f};

    uint2 ra[4], rb[4];
#pragma unroll
    for (int r4 = 0; r4 < 4; r4++) {
        float4 a4 = *(const float4*)(Ag + (size_t)(lr + r4 * 32) * DD + lc);
        float4 b4 = *(const float4*)(Bg + (size_t)(lr + r4 * 32) * DD + lc);
        ssA[r4] += a4.x * a4.x + a4.y * a4.y + a4.z * a4.z + a4.w * a4.w;
        ssB[r4] += b4.x * b4.x + b4.y * b4.y + b4.z * b4.z + b4.w * b4.w;
        ra[r4] = cvt_f4_bf16(a4);
        rb[r4] = cvt_f4_bf16(b4);
    }
    int buf = 0;
#pragma unroll
    for (int r4 = 0; r4 < 4; r4++) {
        *(uint2*)&su.m.As[buf][(lr + r4 * 32) * LDP + lc] = ra[r4];
        *(uint2*)&su.m.Bs[buf][(lr + r4 * 32) * LDP + lc] = rb[r4];
    }
    __syncthreads();

    int a_row_in = (lane & 15);
    int a_koff   = (lane >> 4) * 8;
    int b_row_in = ((lane >> 4) << 3) + (lane & 7);
    int b_koff   = ((lane >> 3) & 1) * 8;

    for (int kt = 0; kt < DD / KT; kt++) {
        int nk = kt + 1;
        if (nk < DD / KT) {
#pragma unroll
            for (int r4 = 0; r4 < 4; r4++) {
                float4 a4 = *(const float4*)(Ag + (size_t)(lr + r4 * 32) * DD + nk * KT + lc);
                float4 b4 = *(const float4*)(Bg + (size_t)(lr + r4 * 32) * DD + nk * KT + lc);
                ssA[r4] += a4.x * a4.x + a4.y * a4.y + a4.z * a4.z + a4.w * a4.w;
                ssB[r4] += b4.x * b4.x + b4.y * b4.y + b4.z * b4.z + b4.w * b4.w;
                ra[r4] = cvt_f4_bf16(a4);
                rb[r4] = cvt_f4_bf16(b4);
            }
        }
#pragma unroll
        for (int kk = 0; kk < KT; kk += 16) {
            uint32_t af[4][4];
            uint32_t bf2[2][4];
#pragma unroll
            for (int mt = 0; mt < 4; mt++) {
                int arow = wm * 64 + mt * 16 + a_row_in;
                uint32_t addr = smem_u32(&su.m.As[buf][arow * LDP + kk + a_koff]);
                ldsm_x4(af[mt][0], af[mt][1], af[mt][2], af[mt][3], addr);
            }
#pragma unroll
            for (int ntp = 0; ntp < 2; ntp++) {
                int brow = wn * 32 + ntp * 16 + b_row_in;
                uint32_t addr = smem_u32(&su.m.Bs[buf][brow * LDP + kk + b_koff]);
                ldsm_x4(bf2[ntp][0], bf2[ntp][1], bf2[ntp][2], bf2[ntp][3], addr);
            }
#pragma unroll
            for (int mt = 0; mt < 4; mt++)
#pragma unroll
                for (int nt = 0; nt < 4; nt++) {
                    uint32_t b0 = bf2[nt >> 1][(nt & 1) * 2];
                    uint32_t b1 = bf2[nt >> 1][(nt & 1) * 2 + 1];
                    asm volatile(
                        "mma.sync.aligned.m16n8k16.row.col.f32.bf16.bf16.f32 "
                        "{%0,%1,%2,%3}, {%4,%5,%6,%7}, {%8,%9}, {%0,%1,%2,%3};\n"
                        : "+f"(acc[mt][nt][0]), "+f"(acc[mt][nt][1]),
                          "+f"(acc[mt][nt][2]), "+f"(acc[mt][nt][3])
                        : "r"(af[mt][0]), "r"(af[mt][1]), "r"(af[mt][2]), "r"(af[mt][3]),
                          "r"(b0), "r"(b1));
                }
        }
        if (nk < DD / KT) {
            int nbuf = buf ^ 1;
#pragma unroll
            for (int r4 = 0; r4 < 4; r4++) {
                *(uint2*)&su.m.As[nbuf][(lr + r4 * 32) * LDP + lc] = ra[r4];
                *(uint2*)&su.m.Bs[nbuf][(lr + r4 * 32) * LDP + lc] = rb[r4];
            }
        }
        __syncthreads();
        buf ^= 1;
    }

    // Per-row inverse norms (8 consecutive lanes share each row)
#pragma unroll
    for (int r4 = 0; r4 < 4; r4++) {
#pragma unroll
        for (int o = 1; o < 8; o <<= 1) {
            ssA[r4] += __shfl_xor_sync(0xffffffffu, ssA[r4], o);
            ssB[r4] += __shfl_xor_sync(0xffffffffu, ssB[r4], o);
        }
        if ((lane & 7) == 0) {
            int row = lr + r4 * 32;
            invA_s[row] = 1.0f / fmaxf(sqrtf(ssA[r4]), 1e-12f);
            invB_s[row] = 1.0f / fmaxf(sqrtf(ssB[r4]), 1e-12f);
        }
    }
    __syncthreads();

    // Epilogue: two 64-row halves through smem staging, then diagonal copy-out.
    float* dd = g_distD + (size_t)b * 512 * 256;
#pragma unroll 1
    for (int half = 0; half < 2; half++) {
        if (wm == half) {
#pragma unroll
            for (int mt = 0; mt < 4; mt++) {
#pragma unroll
                for (int nt = 0; nt < 4; nt++) {
                    int li = mt * 16 + gid;             // 0..63 within half
                    int lj = wn * 32 + nt * 8 + tig * 2;
                    float ia0 = invA_s[half * 64 + li];
                    float ia1 = invA_s[half * 64 + li + 8];
                    float ib0 = invB_s[lj];
                    float ib1 = invB_s[lj + 1];
                    float2 v0, v1;
                    v0.x = 1.0f - fminf(fmaxf(acc[mt][nt][0] * ia0 * ib0, -1.f), 1.f);
                    v0.y = 1.0f - fminf(fmaxf(acc[mt][nt][1] * ia0 * ib1, -1.f), 1.f);
                    v1.x = 1.0f - fminf(fmaxf(acc[mt][nt][2] * ia1 * ib0, -1.f), 1.f);
                    v1.y = 1.0f - fminf(fmaxf(acc[mt][nt][3] * ia1 * ib1, -1.f), 1.f);
                    *(float2*)&su.stage[li * STG_LD + lj]       = v0;
                    *(float2*)&su.stage[(li + 8) * STG_LD + lj] = v1;
                }
            }
        }
        __syncthreads();
        // copy 191 diagonals (d = li+jj, li in [0,63], jj in [0,127])
        int kbase = i0 + half * 64 + j0;
        for (int d = w; d < 191; d += 8) {
            int lo = (d > 127) ? d - 127 : 0;
            int hi = (d < 63) ? d : 63;
            int L  = hi - lo + 1;
            float* dst = dd + (size_t)(kbase + d) * 256 + j0;
#pragma unroll 2
            for (int idx = lane; idx < L; idx += 32) {
                int li = lo + idx;
                int jj = d - li;
                dst[jj] = su.stage[li * STG_LD + jj];
            }
        }
        __syncthreads();
    }
}

// ---------------------------------------------------------------------------
// Kernel 2: banded DTW, anti-diagonal wavefront (no scans: one shfl.up + 3-way
// min per step). One warp per batch, lane owns 8 columns; 16-deep cp.async
// diagonal ring. 2 warps per block.
// ---------------------------------------------------------------------------
#define SDEPTH 16

__global__ __launch_bounds__(64) void dtw_kernel(float* __restrict__ out) {
    __shared__ float ring[2][SDEPTH][256];
    int w     = threadIdx.x >> 5;
    int lane  = threadIdx.x & 31;
    int batch = blockIdx.x * 2 + w;
    const float* dd = g_distD + (size_t)batch * 512 * 256;
    int jbase = lane * 8;

    for (int s = 0; s < SDEPTH; s++) {
        uint32_t sa = smem_u32(&ring[w][s][jbase]);
        const float* src = dd + (size_t)s * 256 + jbase;
        cp16(sa, src);
        cp16(sa + 16, src + 4);
        asm volatile("cp.async.commit_group;\n" ::: "memory");
    }

    float d1[8], d2[8];
#pragma unroll
    for (int u = 0; u < 8; u++) { d1[u] = BIGF; d2[u] = BIGF; }

    for (int k = 0; k < 511; k++) {
        asm volatile("cp.async.wait_group 15;\n" ::: "memory");
        float cur[8];
        const float* slot = &ring[w][k & (SDEPTH - 1)][jbase];
#pragma unroll
        for (int u = 0; u < 8; u++) cur[u] = slot[u];

        int nk = k + SDEPTH;
        if (nk < 512) {
            uint32_t sa = smem_u32(&ring[w][nk & (SDEPTH - 1)][jbase]);
            const float* src = dd + (size_t)nk * 256 + jbase;
            cp16(sa, src);
            cp16(sa + 16, src + 4);
        }
        asm volatile("cp.async.commit_group;\n" ::: "memory");

        float pl1 = __shfl_up_sync(0xffffffffu, d1[7], 1);
        float pl2 = __shfl_up_sync(0xffffffffu, d2[7], 1);

        float nv[8];
#pragma unroll
        for (int u = 0; u < 8; u++) {
            int j = jbase + u;
            int i = k - j;
            float d  = cur[u];
            float lf = u ? d1[u - 1] : pl1;
            float ul = u ? d2[u - 1] : pl2;
            float up = d1[u];
            float v;
            if (i == 0) {
                v = (j == 0) ? d : ((j <= RBAND) ? lf + d : BIGF);
            } else if (j == 0) {
                v = (i >= 1 && i <= RBAND) ? up + d : BIGF;
            } else {
                bool act = (i >= 1) && (i <= 255) && (j >= i - RBAND) && (j <= i + RBAND);
                v = act ? fminf(fminf(up, lf), ul) + d : BIGF;
            }
            nv[u] = v;
        }
#pragma unroll
        for (int u = 0; u < 8; u++) { d2[u] = d1[u]; d1[u] = nv[u]; }
    }

    if (lane == 31) out[batch] = d1[7];  // cell (255,255), diagonal 510
}

// ---------------------------------------------------------------------------
extern "C" void kernel_launch(void* const* d_in, const int* in_sizes, int n_in,
                              void* d_out, int out_size) {
    const float* s1 = (const float*)d_in[0];
    const float* s2 = (const float*)d_in[1];
    float* out = (float*)d_out;

    dim3 g(2, 2, BB);
    gemm_kernel<<<g, 256>>>(s1, s2);

    dtw_kernel<<<128, 64>>>(out);
}

// round 6
// speedup vs baseline: 1.2569x; 1.2569x over previous
#include <cuda_runtime.h>
#include <cuda_bf16.h>
#include <cstdint>

#define BB 256
#define NN 256
#define MM 256
#define DD 1024
#define RBAND 128
#define BIGF 1e30f

// dist row-major [b][i][j]
__device__ float g_dist[(size_t)BB * 256 * 256];

static __device__ __forceinline__ uint32_t smem_u32(const void* p) {
    uint32_t a;
    asm("{ .reg .u64 t; cvta.to.shared.u64 t, %1; cvt.u32.u64 %0, t; }" : "=r"(a) : "l"(p));
    return a;
}
static __device__ __forceinline__ void ldsm_x4(uint32_t& r0, uint32_t& r1, uint32_t& r2,
                                               uint32_t& r3, uint32_t addr) {
    asm volatile("ldmatrix.sync.aligned.m8n8.x4.shared.b16 {%0,%1,%2,%3}, [%4];"
                 : "=r"(r0), "=r"(r1), "=r"(r2), "=r"(r3) : "r"(addr));
}
static __device__ __forceinline__ uint2 cvt_f4_bf16(float4 a) {
    __nv_bfloat162 p0 = __floats2bfloat162_rn(a.x, a.y);
    __nv_bfloat162 p1 = __floats2bfloat162_rn(a.z, a.w);
    uint2 w;
    w.x = *reinterpret_cast<unsigned int*>(&p0);
    w.y = *reinterpret_cast<unsigned int*>(&p1);
    return w;
}

// ---------------------------------------------------------------------------
// Fused kernel: normalization + batched GEMM sim = A @ B^T.
// Grid (2,1,B): CTA computes 128(M) x 256(N) -> per-batch DRAM read 3MB
// (was 4MB with 2x2 tiling). 512 thr = 16 warps (2M x 8N), warp tile 64x32,
// K-tile 32, double-buffered smem pad-40, ldmatrix fragments.
// Per-row sum-of-squares accumulated during fp32 loads; epilogue applies
// 1/(|x||y|), clamps, stores dist row-major as float2.
// ---------------------------------------------------------------------------
#define KT 32
#define LDP 40
#define AS_ELE (128 * LDP)
#define BS_ELE (256 * LDP)
#define GEMM_SMEM ((2 * AS_ELE + 2 * BS_ELE) * 2 + (128 + 256) * 4)

__global__ __launch_bounds__(512, 1) void gemm_kernel(const float* __restrict__ s1,
                                                      const float* __restrict__ s2) {
    extern __shared__ __align__(16) char sm_raw[];
    __nv_bfloat16* As = (__nv_bfloat16*)sm_raw;            // [2][128*LDP]
    __nv_bfloat16* Bs = As + 2 * AS_ELE;                   // [2][256*LDP]
    float* invA_s = (float*)(Bs + 2 * BS_ELE);             // [128]
    float* invB_s = invA_s + 128;                          // [256]

    int b  = blockIdx.z;
    int i0 = blockIdx.x * 128;
    int t    = threadIdx.x;
    int lane = t & 31;
    int w    = t >> 5;
    int wm = w & 1;          // 0..1 (M)
    int wn = w >> 1;         // 0..7 (N)
    int gid = lane >> 2;
    int tig = lane & 3;

    const float* Ag = s1 + (size_t)b * NN * DD + (size_t)i0 * DD;
    const float* Bg = s2 + (size_t)b * MM * DD;

    int lr = t >> 3;        // 0..63
    int lc = (t & 7) * 4;   // 0..28

    float acc[4][4][4];
#pragma unroll
    for (int mt = 0; mt < 4; mt++)
#pragma unroll
        for (int nt = 0; nt < 4; nt++)
#pragma unroll
            for (int c = 0; c < 4; c++) acc[mt][nt][c] = 0.f;

    float ssA[2] = {0.f, 0.f};
    float ssB[4] = {0.f, 0.f, 0.f, 0.f};

    uint2 ra[2], rb[4];
#pragma unroll
    for (int q = 0; q < 2; q++) {
        float4 a4 = *(const float4*)(Ag + (size_t)(lr + q * 64) * DD + lc);
        ssA[q] += a4.x * a4.x + a4.y * a4.y + a4.z * a4.z + a4.w * a4.w;
        ra[q] = cvt_f4_bf16(a4);
    }
#pragma unroll
    for (int q = 0; q < 4; q++) {
        float4 b4 = *(const float4*)(Bg + (size_t)(lr + q * 64) * DD + lc);
        ssB[q] += b4.x * b4.x + b4.y * b4.y + b4.z * b4.z + b4.w * b4.w;
        rb[q] = cvt_f4_bf16(b4);
    }
    int buf = 0;
#pragma unroll
    for (int q = 0; q < 2; q++)
        *(uint2*)&As[buf * AS_ELE + (lr + q * 64) * LDP + lc] = ra[q];
#pragma unroll
    for (int q = 0; q < 4; q++)
        *(uint2*)&Bs[buf * BS_ELE + (lr + q * 64) * LDP + lc] = rb[q];
    __syncthreads();

    int a_row_in = (lane & 15);
    int a_koff   = (lane >> 4) * 8;
    int b_row_in = ((lane >> 4) << 3) + (lane & 7);
    int b_koff   = ((lane >> 3) & 1) * 8;

    for (int kt = 0; kt < DD / KT; kt++) {
        int nk = kt + 1;
        if (nk < DD / KT) {
#pragma unroll
            for (int q = 0; q < 2; q++) {
                float4 a4 = *(const float4*)(Ag + (size_t)(lr + q * 64) * DD + nk * KT + lc);
                ssA[q] += a4.x * a4.x + a4.y * a4.y + a4.z * a4.z + a4.w * a4.w;
                ra[q] = cvt_f4_bf16(a4);
            }
#pragma unroll
            for (int q = 0; q < 4; q++) {
                float4 b4 = *(const float4*)(Bg + (size_t)(lr + q * 64) * DD + nk * KT + lc);
                ssB[q] += b4.x * b4.x + b4.y * b4.y + b4.z * b4.z + b4.w * b4.w;
                rb[q] = cvt_f4_bf16(b4);
            }
        }
#pragma unroll
        for (int kk = 0; kk < KT; kk += 16) {
            uint32_t af[4][4];
            uint32_t bf2[2][4];
#pragma unroll
            for (int mt = 0; mt < 4; mt++) {
                int arow = wm * 64 + mt * 16 + a_row_in;
                uint32_t addr = smem_u32(&As[buf * AS_ELE + arow * LDP + kk + a_koff]);
                ldsm_x4(af[mt][0], af[mt][1], af[mt][2], af[mt][3], addr);
            }
#pragma unroll
            for (int ntp = 0; ntp < 2; ntp++) {
                int brow = wn * 32 + ntp * 16 + b_row_in;
                uint32_t addr = smem_u32(&Bs[buf * BS_ELE + brow * LDP + kk + b_koff]);
                ldsm_x4(bf2[ntp][0], bf2[ntp][1], bf2[ntp][2], bf2[ntp][3], addr);
            }
#pragma unroll
            for (int mt = 0; mt < 4; mt++)
#pragma unroll
                for (int nt = 0; nt < 4; nt++) {
                    uint32_t b0 = bf2[nt >> 1][(nt & 1) * 2];
                    uint32_t b1 = bf2[nt >> 1][(nt & 1) * 2 + 1];
                    asm volatile(
                        "mma.sync.aligned.m16n8k16.row.col.f32.bf16.bf16.f32 "
                        "{%0,%1,%2,%3}, {%4,%5,%6,%7}, {%8,%9}, {%0,%1,%2,%3};\n"
                        : "+f"(acc[mt][nt][0]), "+f"(acc[mt][nt][1]),
                          "+f"(acc[mt][nt][2]), "+f"(acc[mt][nt][3])
                        : "r"(af[mt][0]), "r"(af[mt][1]), "r"(af[mt][2]), "r"(af[mt][3]),
                          "r"(b0), "r"(b1));
                }
        }
        if (nk < DD / KT) {
            int nbuf = buf ^ 1;
#pragma unroll
            for (int q = 0; q < 2; q++)
                *(uint2*)&As[nbuf * AS_ELE + (lr + q * 64) * LDP + lc] = ra[q];
#pragma unroll
            for (int q = 0; q < 4; q++)
                *(uint2*)&Bs[nbuf * BS_ELE + (lr + q * 64) * LDP + lc] = rb[q];
        }
        __syncthreads();
        buf ^= 1;
    }

    // Per-row inverse norms (8 consecutive lanes share each row)
#pragma unroll
    for (int q = 0; q < 2; q++) {
#pragma unroll
        for (int o = 1; o < 8; o <<= 1) ssA[q] += __shfl_xor_sync(0xffffffffu, ssA[q], o);
    }
#pragma unroll
    for (int q = 0; q < 4; q++) {
#pragma unroll
        for (int o = 1; o < 8; o <<= 1) ssB[q] += __shfl_xor_sync(0xffffffffu, ssB[q], o);
    }
    if ((t & 7) == 0) {
#pragma unroll
        for (int q = 0; q < 2; q++)
            invA_s[lr + q * 64] = 1.0f / fmaxf(sqrtf(ssA[q]), 1e-12f);
#pragma unroll
        for (int q = 0; q < 4; q++)
            invB_s[lr + q * 64] = 1.0f / fmaxf(sqrtf(ssB[q]), 1e-12f);
    }
    __syncthreads();

    // Epilogue: sim = acc * invA[i] * invB[j]; dist = 1 - clamp(sim), float2.
    float* dT = g_dist + (size_t)b * 65536;
#pragma unroll
    for (int mt = 0; mt < 4; mt++) {
#pragma unroll
        for (int nt = 0; nt < 4; nt++) {
            int li = wm * 64 + mt * 16 + gid;
            int j  = wn * 32 + nt * 8 + tig * 2;
            float ia0 = invA_s[li];
            float ia1 = invA_s[li + 8];
            float ib0 = invB_s[j];
            float ib1 = invB_s[j + 1];
            float2 v0, v1;
            v0.x = 1.0f - fminf(fmaxf(acc[mt][nt][0] * ia0 * ib0, -1.f), 1.f);
            v0.y = 1.0f - fminf(fmaxf(acc[mt][nt][1] * ia0 * ib1, -1.f), 1.f);
            v1.x = 1.0f - fminf(fmaxf(acc[mt][nt][2] * ia1 * ib0, -1.f), 1.f);
            v1.y = 1.0f - fminf(fmaxf(acc[mt][nt][3] * ia1 * ib1, -1.f), 1.f);
            int i = i0 + li;
            *(float2*)&dT[(size_t)i * 256 + j]       = v0;
            *(float2*)&dT[(size_t)(i + 8) * 256 + j] = v1;
        }
    }
}

// ---------------------------------------------------------------------------
// Kernel 2: banded DTW, row-streaming min-plus scan. One warp per batch; lane
// owns 8 columns. Rows prefetched 2 deep in REGISTERS (plain LDG.128, no
// cp.async ring -> no wait_group in the dependence chain, 4 loads/thread
// outstanding, well under the per-warp cap).
// ---------------------------------------------------------------------------
__global__ __launch_bounds__(128) void dtw_kernel(float* __restrict__ out) {
    int w     = threadIdx.x >> 5;
    int lane  = threadIdx.x & 31;
    int batch = blockIdx.x * 4 + w;
    const float* E = g_dist + (size_t)batch * 65536;
    int cbase = lane * 8;

    // register ring: cur (row r), nx (row r+1); row r+2 loaded in-loop
    float4 c0 = *(const float4*)(E + cbase);
    float4 c1 = *(const float4*)(E + cbase + 4);
    float4 n0 = *(const float4*)(E + 256 + cbase);
    float4 n1 = *(const float4*)(E + 256 + cbase + 4);

    float prev[8];

    for (int r = 0; r < 256; r++) {
        float4 f0, f1;
        if (r + 2 < 256) {
            const float* src = E + (size_t)(r + 2) * 256 + cbase;
            f0 = *(const float4*)(src);
            f1 = *(const float4*)(src + 4);
        }
        float e[8];
        e[0] = c0.x; e[1] = c0.y; e[2] = c0.z; e[3] = c0.w;
        e[4] = c1.x; e[5] = c1.y; e[6] = c1.z; e[7] = c1.w;

        if (r == 0) {
            float ps[8];
            float run = 0.f;
#pragma unroll
            for (int u = 0; u < 8; u++) { run += e[u]; ps[u] = run; }
            float acc = run;
#pragma unroll
            for (int d = 1; d < 32; d <<= 1) {
                float p = __shfl_up_sync(0xffffffffu, acc, d);
                if (lane >= d) acc += p;
            }
            float excl = acc - run;
#pragma unroll
            for (int u = 0; u < 8; u++) {
                float tv = excl + ps[u];
                prev[u] = (cbase + u <= RBAND) ? tv : BIGF;
            }
        } else {
            float pl = __shfl_up_sync(0xffffffffu, prev[7], 1);
            if (lane == 0) pl = BIGF;
            float bb[8], ss[8];
#pragma unroll
            for (int u = 0; u < 8; u++) {
                int c = cbase + u;
                float pjm1 = u ? prev[u - 1] : pl;
                bool ib = (c >= 1) && (c >= r - RBAND) && (c <= r + RBAND);
                bb[u] = ib ? fminf(prev[u], pjm1) + e[u] : BIGF;
                ss[u] = ib ? e[u] : BIGF;
            }
            if (lane == 0) {
                bb[0] = (r <= RBAND) ? prev[0] + e[0] : BIGF;
                ss[0] = BIGF;
            }
            float tl[8], P[8];
            tl[0] = bb[0];
            P[0]  = ss[0];
#pragma unroll
            for (int u = 1; u < 8; u++) {
                tl[u] = fminf(bb[u], tl[u - 1] + ss[u]);
                P[u]  = P[u - 1] + ss[u];
            }
            float S = P[7], T = tl[7];
#pragma unroll
            for (int d = 1; d < 32; d <<= 1) {
                float Sp = __shfl_up_sync(0xffffffffu, S, d);
                float Tp = __shfl_up_sync(0xffffffffu, T, d);
                if (lane >= d) {
                    T = fminf(T, Tp + S);
                    S = S + Sp;
                }
            }
            float cin = __shfl_up_sync(0xffffffffu, T, 1);
            if (lane == 0) cin = BIGF;
#pragma unroll
            for (int u = 0; u < 8; u++) prev[u] = fminf(tl[u], cin + P[u]);
        }

        c0 = n0; c1 = n1;
        n0 = f0; n1 = f1;
    }

    if (lane == 31) out[batch] = prev[7];
}

// ---------------------------------------------------------------------------
extern "C" void kernel_launch(void* const* d_in, const int* in_sizes, int n_in,
                              void* d_out, int out_size) {
    const float* s1 = (const float*)d_in[0];
    const float* s2 = (const float*)d_in[1];
    float* out = (float*)d_out;

    cudaFuncSetAttribute(gemm_kernel, cudaFuncAttributeMaxDynamicSharedMemorySize, GEMM_SMEM);
    dim3 g(2, 1, BB);
    gemm_kernel<<<g, 512, GEMM_SMEM>>>(s1, s2);

    dtw_kernel<<<64, 128>>>(out);
}